// round 9
// baseline (speedup 1.0000x reference)
#include <cuda_runtime.h>
#include <cuda_fp16.h>
#include <cstdint>

#define NN 100000
#define NE 1600000
#define HH 64
#define NLAYERS 3

// ---------------- device scratch ----------------
__device__ float4 g_h4[NN * 16];     // h: (N, 64) fp32
__device__ float4 g_agg4[NN * 16];   // agg: (N, 64) fp32
__device__ __half2 g_ah[NN * 32];    // a[n] = h[n] @ W1[0:64] + e_b1 (fp16)
__device__ __half2 g_bh[NN * 32];    // b[n] = h[n] @ W1[64:128]      (fp16)
__device__ float  g_dx[NN * 3];
__device__ float4 g_tmean4[16];

// ---------------- helpers ----------------
__device__ __forceinline__ float siluf(float v) {
    float th;
    float hv = 0.5f * v;
    asm("tanh.approx.f32 %0, %1;" : "=f"(th) : "f"(hv));
    return fmaf(hv, th, hv);
}
__device__ __forceinline__ float silux(float v) {
    return __fdividef(v, 1.0f + __expf(-v));
}
__device__ __forceinline__ void red2(float *p, float a, float b) {
    asm volatile("red.global.add.v2.f32 [%0], {%1,%2};" ::"l"(p), "f"(a), "f"(b)
                 : "memory");
}
__device__ __forceinline__ void red1(float *p, float a) {
    asm volatile("red.global.add.f32 [%0], %1;" ::"l"(p), "f"(a) : "memory");
}
__device__ __forceinline__ uint32_t packh(float a, float b) {
    __half2 h = __floats2half2_rn(a, b);
    return *reinterpret_cast<uint32_t *>(&h);
}
// pair-slot index for fp16x2 word w (= k/2) within a row
__device__ __forceinline__ int pslot(int w) {
    return 8 * (w >> 3) + 2 * (w & 3) + ((w >> 2) & 1);
}
__device__ __forceinline__ void barp(int id) {
    asm volatile("bar.sync %0, %1;" ::"r"(id), "r"(64) : "memory");
}
__device__ __forceinline__ void mma_f16(float (&d)[4], uint32_t a0, uint32_t a1,
                                        uint32_t a2, uint32_t a3, uint32_t b0,
                                        uint32_t b1) {
    asm volatile(
        "mma.sync.aligned.m16n8k16.row.col.f32.f16.f16.f32 "
        "{%0,%1,%2,%3}, {%4,%5,%6,%7}, {%8,%9}, {%0,%1,%2,%3};\n"
        : "+f"(d[0]), "+f"(d[1]), "+f"(d[2]), "+f"(d[3])
        : "r"(a0), "r"(a1), "r"(a2), "r"(a3), "r"(b0), "r"(b1));
}

// 32 x (16*KS16) A @ B (64 cols), fp16x2 pair-slot layout
template <int SA, int SB, int KS16>
__device__ __forceinline__ void gemmH(float (&acc)[2][8][4],
                                      const uint32_t *__restrict__ A,
                                      const uint32_t *__restrict__ B, int g,
                                      int q) {
#pragma unroll
    for (int ks = 0; ks < KS16; ks++) {
        uint2 bf[8];
#pragma unroll
        for (int n = 0; n < 8; n++)
            bf[n] = *(const uint2 *)(B + (8 * n + g) * SB + 8 * ks + 2 * q);
#pragma unroll
        for (int m = 0; m < 2; m++) {
            const uint32_t *ap = A + (16 * m + g) * SA + 8 * ks + 2 * q;
            uint2 lo = *(const uint2 *)ap;
            uint2 hi = *(const uint2 *)(ap + 8 * SA);
#pragma unroll
            for (int n = 0; n < 8; n++)
                mma_f16(acc[m][n], lo.x, hi.x, lo.y, hi.y, bf[n].x, bf[n].y);
        }
    }
}
// N=32 half-width variant (warp-pair cooperative)
template <int SA, int SB, int KS16>
__device__ __forceinline__ void gemmH2(float (&acc)[2][4][4],
                                       const uint32_t *__restrict__ A,
                                       const uint32_t *__restrict__ B, int g,
                                       int q) {
#pragma unroll
    for (int ks = 0; ks < KS16; ks++) {
        uint2 bf[4];
#pragma unroll
        for (int n = 0; n < 4; n++)
            bf[n] = *(const uint2 *)(B + (8 * n + g) * SB + 8 * ks + 2 * q);
#pragma unroll
        for (int m = 0; m < 2; m++) {
            const uint32_t *ap = A + (16 * m + g) * SA + 8 * ks + 2 * q;
            uint2 lo = *(const uint2 *)ap;
            uint2 hi = *(const uint2 *)(ap + 8 * SA);
#pragma unroll
            for (int n = 0; n < 4; n++)
                mma_f16(acc[m][n], lo.x, hi.x, lo.y, hi.y, bf[n].x, bf[n].y);
        }
    }
}
__device__ __forceinline__ void zacc(float (&acc)[2][8][4]) {
#pragma unroll
    for (int m = 0; m < 2; m++)
#pragma unroll
        for (int n = 0; n < 8; n++)
#pragma unroll
            for (int v = 0; v < 4; v++) acc[m][n][v] = 0.f;
}
__device__ __forceinline__ void zacc2(float (&acc)[2][4][4]) {
#pragma unroll
    for (int m = 0; m < 2; m++)
#pragma unroll
        for (int n = 0; n < 4; n++)
#pragma unroll
            for (int v = 0; v < 4; v++) acc[m][n][v] = 0.f;
}
__device__ __forceinline__ void cp_s(float *dst, const float *__restrict__ src,
                                     int nfloats, int tid, int nthr) {
    const float4 *s4 = (const float4 *)src;
    float4 *d4 = (float4 *)dst;
    for (int k = tid; k < (nfloats >> 2); k += nthr) d4[k] = s4[k];
}
// stage K x 64 row-major fp32 weights into fp16x2 pair-slot [64][stride]
__device__ __forceinline__ void stage_w16(uint32_t *dst, const float *__restrict__ W,
                                          int kwords, int stride, int tid,
                                          int nthr) {
    for (int idx = tid; idx < 64 * kwords; idx += nthr) {
        int n = idx / kwords, w = idx % kwords;
        dst[n * stride + pslot(w)] =
            packh(W[(2 * w) * 64 + n], W[(2 * w + 1) * 64 + n]);
    }
}

// ---------------- time-embedding mean ----------------
__global__ void tmean_kernel(const float *__restrict__ t,
                             const float *__restrict__ w1,
                             const float *__restrict__ b1,
                             const float *__restrict__ w2,
                             const float *__restrict__ b2) {
    __shared__ float sS[16 * 64];
    int j = threadIdx.x;
    float w1j = w1[j], b1j = b1[j];
    for (int b = 0; b < 16; b++) sS[b * 64 + j] = silux(t[b] * w1j + b1j);
    __syncthreads();
    float accm = 0.f;
    for (int b = 0; b < 16; b++) {
        float s = b2[j];
        for (int k = 0; k < 64; k++) s += sS[b * 64 + k] * w2[k * 64 + j];
        accm += s;
    }
    ((float *)g_tmean4)[j] = accm * (1.0f / 16.0f);
}

// ---------------- init ----------------
__global__ void init_kernel(const float *__restrict__ x, const int *__restrict__ z,
                            const float *__restrict__ emb, float *__restrict__ out) {
    int tid = blockIdx.x * blockDim.x + threadIdx.x;
    int stride = gridDim.x * blockDim.x;
    const float4 *emb4 = (const float4 *)emb;
    for (int idx = tid; idx < NN * 16; idx += stride) {
        int i = idx >> 4, qq = idx & 15;
        float4 e = emb4[z[i] * 16 + qq];
        float4 tm = g_tmean4[qq];
        float4 r;
        r.x = e.x + tm.x; r.y = e.y + tm.y; r.z = e.z + tm.z; r.w = e.w + tm.w;
        g_h4[idx] = r;
        g_agg4[idx] = make_float4(0.f, 0.f, 0.f, 0.f);
    }
    for (int idx = tid; idx < NN * 3; idx += stride) {
        out[idx] = x[idx];
        g_dx[idx] = 0.f;
    }
}

// ---------------- pre0: a,b for layer 0 (fp16 tensor core) ----------------
#define PR_AT 0
#define PR_BT 2560
#define PR_EB1 5120
#define PR_WARP 5184
#define PR_WARP_WORDS 1280
#define PRE_SMEM_BYTES ((PR_WARP + 8 * PR_WARP_WORDS) * 4)

__global__ void __launch_bounds__(256, 2)
pre0_kernel(const float *__restrict__ W1, const float *__restrict__ B1) {
    extern __shared__ float sm[];
    uint32_t *smu = (uint32_t *)sm;
    int tid = threadIdx.x;
    stage_w16(smu + PR_AT, W1, 32, 40, tid, 256);
    stage_w16(smu + PR_BT, W1 + 64 * 64, 32, 40, tid, 256);
    cp_s(sm + PR_EB1, B1, 64, tid, 256);
    __syncthreads();

    const int lane = tid & 31, wid = tid >> 5;
    const int g = lane >> 2, q = lane & 3;
    uint32_t *buf = smu + PR_WARP + wid * PR_WARP_WORDS;
    const float *gh = (const float *)g_h4;
    const int sl = pslot(lane);

    int gwarp = blockIdx.x * 8 + wid;
    int nwarps = gridDim.x * 8;
    for (int i0 = gwarp * 32; i0 < NN; i0 += nwarps * 32) {
#pragma unroll
        for (int t = 0; t < 32; t++) {
            float2 hv = *(const float2 *)(gh + (size_t)(i0 + t) * HH + 2 * lane);
            buf[t * 40 + sl] = packh(hv.x, hv.y);
        }
        __syncwarp();
        float acc[2][8][4];
        zacc(acc);
        gemmH<40, 40, 4>(acc, buf, smu + PR_AT, g, q);
#pragma unroll
        for (int m = 0; m < 2; m++) {
            int r0 = 16 * m + g, r1 = r0 + 8;
#pragma unroll
            for (int n = 0; n < 8; n++) {
                int w = 4 * n + q;
                float2 bb = *(const float2 *)(sm + PR_EB1 + 2 * w);
                g_ah[(size_t)(i0 + r0) * 32 + w] =
                    __floats2half2_rn(acc[m][n][0] + bb.x, acc[m][n][1] + bb.y);
                g_ah[(size_t)(i0 + r1) * 32 + w] =
                    __floats2half2_rn(acc[m][n][2] + bb.x, acc[m][n][3] + bb.y);
            }
        }
        zacc(acc);
        gemmH<40, 40, 4>(acc, buf, smu + PR_BT, g, q);
#pragma unroll
        for (int m = 0; m < 2; m++) {
            int r0 = 16 * m + g, r1 = r0 + 8;
#pragma unroll
            for (int n = 0; n < 8; n++) {
                int w = 4 * n + q;
                g_bh[(size_t)(i0 + r0) * 32 + w] =
                    __floats2half2_rn(acc[m][n][0], acc[m][n][1]);
                g_bh[(size_t)(i0 + r1) * 32 + w] =
                    __floats2half2_rn(acc[m][n][2], acc[m][n][3]);
            }
        }
        __syncwarp();
    }
}

// ---------------- edge kernel (fp16 TC, warp-pair N-split, 3 CTA/SM) -------
#define E_W2T 0
#define E_C1T 2560
#define E_B2 5120
#define E_CB1 5184
#define E_C2 5248
#define E_W129 5312
#define E_CB2 5376
#define E_WARP 5384
#define E_PAIR_WORDS 1344   /* m1s 1280 + cwbuf 64 */
#define EDGE_SMEM_BYTES ((E_WARP + 4 * E_PAIR_WORDS) * 4)

__global__ void __launch_bounds__(256, 3)
edge_kernel(const float *__restrict__ xin, const int *__restrict__ ei,
            const float *__restrict__ W1, const float *__restrict__ W2,
            const float *__restrict__ B2, const float *__restrict__ C1,
            const float *__restrict__ Cb1, const float *__restrict__ C2,
            const float *__restrict__ Cb2) {
    extern __shared__ float sm[];
    uint32_t *smu = (uint32_t *)sm;
    int tid = threadIdx.x;

    stage_w16(smu + E_W2T, W2, 32, 40, tid, 256);
    stage_w16(smu + E_C1T, C1, 32, 40, tid, 256);
    cp_s(sm + E_B2, B2, 64, tid, 256);
    cp_s(sm + E_CB1, Cb1, 64, tid, 256);
    cp_s(sm + E_C2, C2, 64, tid, 256);
    cp_s(sm + E_W129, W1 + 8192, 64, tid, 256);
    if (tid == 0) sm[E_CB2] = Cb2[0];
    __syncthreads();

    const int lane = tid & 31;
    const int wid = tid >> 5;
    const int pair = wid >> 1;   // 0..3
    const int pw = wid & 1;      // warp within pair: col-half owner
    const int g = lane >> 2;
    const int q = lane & 3;
    const int barid = pair + 1;
    uint32_t *m1s = smu + E_WARP + pair * E_PAIR_WORDS;
    float *cwbuf = sm + E_WARP + pair * E_PAIR_WORDS + 1280;
    const int sl = pslot(lane);

    float *gagg = (float *)g_agg4;

    const float w129x = sm[E_W129 + 2 * lane];
    const float w129y = sm[E_W129 + 2 * lane + 1];
    const float cb2v = sm[E_CB2];
    const uint32_t *W2h = smu + E_W2T + 32 * pw * 40;  // this warp's col-half
    const uint32_t *C1h = smu + E_C1T + 32 * pw * 40;

    int gpair = blockIdx.x * 4 + pair;
    int npairs = gridDim.x * 4;

    for (int eb = gpair * 32; eb < NE; eb += npairs * 32) {
        // ---- phase 0: per-edge meta (lane = edge; both warps redundant) ----
        int e = eb + lane;
        int s = ei[e];
        int d = ei[NE + e];
        float ax = xin[3 * d + 0] - xin[3 * s + 0];
        float ay = xin[3 * d + 1] - xin[3 * s + 1];
        float az = xin[3 * d + 2] - xin[3 * s + 2];
        float d2 = ax * ax + ay * ay + az * az;

        // ---- phase 1: m1 for this warp's 16 edges ----
#pragma unroll
        for (int tt = 0; tt < 16; tt++) {
            int t = 16 * pw + tt;
            int dt = __shfl_sync(0xffffffffu, d, t);
            int st = __shfl_sync(0xffffffffu, s, t);
            float d2t = __shfl_sync(0xffffffffu, d2, t);
            float2 av = __half22float2(g_ah[(size_t)dt * 32 + lane]);
            float2 bv = __half22float2(g_bh[(size_t)st * 32 + lane]);
            float m0 = siluf(fmaf(d2t, w129x, av.x + bv.x));
            float m1v = siluf(fmaf(d2t, w129y, av.y + bv.y));
            m1s[t * 40 + sl] = packh(m0, m1v);
        }
        barp(barid);  // m1 complete

        // ---- GEMM2 (N-half): m = silu(m1 @ W2 + b2) ----
        float acc[2][4][4];
        zacc2(acc);
        gemmH2<40, 40, 4>(acc, m1s, W2h, g, q);
        barp(barid);  // both warps done reading m1 before restage

        // epilogue: silu, red2 agg scatter, restage m (this warp's cols)
#pragma unroll
        for (int m = 0; m < 2; m++) {
            int r0 = 16 * m + g;
            int r1 = r0 + 8;
            int d0 = __shfl_sync(0xffffffffu, d, r0);
            int d1 = __shfl_sync(0xffffffffu, d, r1);
            float *agg0 = gagg + (size_t)d0 * HH;
            float *agg1 = gagg + (size_t)d1 * HH;
#pragma unroll
            for (int n = 0; n < 4; n++) {
                int c0 = 8 * (4 * pw + n) + 2 * q;
                float2 bb = *(const float2 *)(sm + E_B2 + c0);
                float v00 = siluf(acc[m][n][0] + bb.x);
                float v01 = siluf(acc[m][n][1] + bb.y);
                float v10 = siluf(acc[m][n][2] + bb.x);
                float v11 = siluf(acc[m][n][3] + bb.y);
                red2(agg0 + c0, v00, v01);
                red2(agg1 + c0, v10, v11);
                int slw = pslot(16 * pw + 4 * n + q);
                m1s[r0 * 40 + slw] = packh(v00, v01);
                m1s[r1 * 40 + slw] = packh(v10, v11);
            }
        }
        barp(barid);  // m complete

        // ---- coord MLP (N-half): cw = silu(m @ C1 + cb1) @ C2 + cb2 ----
        zacc2(acc);
        gemmH2<40, 40, 4>(acc, m1s, C1h, g, q);

        float cwp[2][2] = {{0.f, 0.f}, {0.f, 0.f}};
#pragma unroll
        for (int m = 0; m < 2; m++)
#pragma unroll
            for (int n = 0; n < 4; n++) {
                int c0 = 8 * (4 * pw + n) + 2 * q;
                float2 cb1v = *(const float2 *)(sm + E_CB1 + c0);
                float2 c2v = *(const float2 *)(sm + E_C2 + c0);
                cwp[m][0] += siluf(acc[m][n][0] + cb1v.x) * c2v.x +
                             siluf(acc[m][n][1] + cb1v.y) * c2v.y;
                cwp[m][1] += siluf(acc[m][n][2] + cb1v.x) * c2v.x +
                             siluf(acc[m][n][3] + cb1v.y) * c2v.y;
            }
#pragma unroll
        for (int ofs = 1; ofs <= 2; ofs <<= 1) {
#pragma unroll
            for (int m = 0; m < 2; m++) {
                cwp[m][0] += __shfl_xor_sync(0xffffffffu, cwp[m][0], ofs);
                cwp[m][1] += __shfl_xor_sync(0xffffffffu, cwp[m][1], ofs);
            }
        }
        if (q == 0) {
#pragma unroll
            for (int m = 0; m < 2; m++) {
                cwbuf[32 * pw + 16 * m + g] = cwp[m][0];
                cwbuf[32 * pw + 16 * m + g + 8] = cwp[m][1];
            }
        }
        barp(barid);  // both col-half partials in cwbuf

        float cw = cwbuf[lane] + cwbuf[32 + lane] + cb2v;
        if ((lane >> 4) == pw) {  // this warp scatters its 16 edges
            red1(&g_dx[3 * d + 0], ax * cw);
            red1(&g_dx[3 * d + 1], ay * cw);
            red1(&g_dx[3 * d + 2], az * cw);
        }
    }
}

// ---------------- node kernel (fp16 TC, fused next-layer pre, 2 CTA/SM) ----
#define ND_W1A 0
#define ND_W1B 2560
#define ND_W2T 5120
#define ND_AT 7680
#define ND_BT 10240
#define ND_NB1 12800
#define ND_NB2 12864
#define ND_EB1 12928
#define ND_WARP 12992
#define ND_WARP_WORDS 1280
#define NODE_SMEM_BYTES ((ND_WARP + 8 * ND_WARP_WORDS) * 4)

__global__ void __launch_bounds__(256, 2)
node_kernel(float *__restrict__ xout, const float *__restrict__ NW1,
            const float *__restrict__ NB1, const float *__restrict__ NW2,
            const float *__restrict__ NB2, const float *__restrict__ EW1n,
            const float *__restrict__ EB1n, int do_pre) {
    extern __shared__ float sm[];
    uint32_t *smu = (uint32_t *)sm;
    int tid = threadIdx.x;

    stage_w16(smu + ND_W1A, NW1, 32, 40, tid, 256);           // nf rows 0..63 (h)
    stage_w16(smu + ND_W1B, NW1 + 64 * 64, 32, 40, tid, 256); // rows 64..127 (agg)
    stage_w16(smu + ND_W2T, NW2, 32, 40, tid, 256);
    if (do_pre) {
        stage_w16(smu + ND_AT, EW1n, 32, 40, tid, 256);
        stage_w16(smu + ND_BT, EW1n + 64 * 64, 32, 40, tid, 256);
    }
    cp_s(sm + ND_NB1, NB1, 64, tid, 256);
    cp_s(sm + ND_NB2, NB2, 64, tid, 256);
    if (do_pre) cp_s(sm + ND_EB1, EB1n, 64, tid, 256);
    __syncthreads();

    const int lane = tid & 31, wid = tid >> 5;
    const int g = lane >> 2, q = lane & 3;
    uint32_t *buf = smu + ND_WARP + wid * ND_WARP_WORDS;
    const int sl = pslot(lane);

    float *gh = (float *)g_h4;
    float *gagg = (float *)g_agg4;

    int gwarp = blockIdx.x * 8 + wid;
    int nwarps = gridDim.x * 8;

    for (int i0 = gwarp * 32; i0 < NN; i0 += nwarps * 32) {
        // stage h fp16 (stride 40)
#pragma unroll
        for (int t = 0; t < 32; t++) {
            float2 hv = *(const float2 *)(gh + (size_t)(i0 + t) * HH + 2 * lane);
            buf[t * 40 + sl] = packh(hv.x, hv.y);
        }
        __syncwarp();

        float acc[2][8][4];
        zacc(acc);
        gemmH<40, 40, 4>(acc, buf, smu + ND_W1A, g, q);
        __syncwarp();

        // stage agg fp16 (overwrite h staging); zero agg
#pragma unroll
        for (int t = 0; t < 32; t++) {
            size_t ro = (size_t)(i0 + t) * HH;
            float2 av = *(const float2 *)(gagg + ro + 2 * lane);
            *(float2 *)(gagg + ro + 2 * lane) = make_float2(0.f, 0.f);
            buf[t * 40 + sl] = packh(av.x, av.y);
        }
        __syncwarp();
        gemmH<40, 40, 4>(acc, buf, smu + ND_W1B, g, q);  // accumulate
        __syncwarp();

        // m1 = silu(acc + nb1) -> restage fp16 stride 40
#pragma unroll
        for (int m = 0; m < 2; m++) {
            int r0 = 16 * m + g, r1 = r0 + 8;
#pragma unroll
            for (int n = 0; n < 8; n++) {
                int c0 = 8 * n + 2 * q;
                float2 bb = *(const float2 *)(sm + ND_NB1 + c0);
                int slw = pslot(4 * n + q);
                buf[r0 * 40 + slw] = packh(siluf(acc[m][n][0] + bb.x),
                                           siluf(acc[m][n][1] + bb.y));
                buf[r1 * 40 + slw] = packh(siluf(acc[m][n][2] + bb.x),
                                           siluf(acc[m][n][3] + bb.y));
            }
        }
        __syncwarp();

        zacc(acc);
        gemmH<40, 40, 4>(acc, buf, smu + ND_W2T, g, q);
        __syncwarp();

        // hnew = h_old + acc + nb2 -> global; restage hnew fp16 for pre
#pragma unroll
        for (int m = 0; m < 2; m++) {
            int r0 = 16 * m + g, r1 = r0 + 8;
            float *h0 = gh + (size_t)(i0 + r0) * HH;
            float *h1 = gh + (size_t)(i0 + r1) * HH;
#pragma unroll
            for (int n = 0; n < 8; n++) {
                int c0 = 8 * n + 2 * q;
                float2 bb = *(const float2 *)(sm + ND_NB2 + c0);
                float2 o0 = *(const float2 *)(h0 + c0);
                float2 o1 = *(const float2 *)(h1 + c0);
                o0.x += acc[m][n][0] + bb.x;
                o0.y += acc[m][n][1] + bb.y;
                o1.x += acc[m][n][2] + bb.x;
                o1.y += acc[m][n][3] + bb.y;
                *(float2 *)(h0 + c0) = o0;
                *(float2 *)(h1 + c0) = o1;
                if (do_pre) {
                    int slw = pslot(4 * n + q);
                    buf[r0 * 40 + slw] = packh(o0.x, o0.y);
                    buf[r1 * 40 + slw] = packh(o1.x, o1.y);
                }
            }
        }
        __syncwarp();

        if (do_pre) {
            zacc(acc);
            gemmH<40, 40, 4>(acc, buf, smu + ND_AT, g, q);
#pragma unroll
            for (int m = 0; m < 2; m++) {
                int r0 = 16 * m + g, r1 = r0 + 8;
#pragma unroll
                for (int n = 0; n < 8; n++) {
                    int w = 4 * n + q;
                    float2 bb = *(const float2 *)(sm + ND_EB1 + 2 * w);
                    g_ah[(size_t)(i0 + r0) * 32 + w] = __floats2half2_rn(
                        acc[m][n][0] + bb.x, acc[m][n][1] + bb.y);
                    g_ah[(size_t)(i0 + r1) * 32 + w] = __floats2half2_rn(
                        acc[m][n][2] + bb.x, acc[m][n][3] + bb.y);
                }
            }
            zacc(acc);
            gemmH<40, 40, 4>(acc, buf, smu + ND_BT, g, q);
#pragma unroll
            for (int m = 0; m < 2; m++) {
                int r0 = 16 * m + g, r1 = r0 + 8;
#pragma unroll
                for (int n = 0; n < 8; n++) {
                    int w = 4 * n + q;
                    g_bh[(size_t)(i0 + r0) * 32 + w] =
                        __floats2half2_rn(acc[m][n][0], acc[m][n][1]);
                    g_bh[(size_t)(i0 + r1) * 32 + w] =
                        __floats2half2_rn(acc[m][n][2], acc[m][n][3]);
                }
            }
        }

        // x += dx; reset dx (lane = node)
        int i = i0 + lane;
#pragma unroll
        for (int k = 0; k < 3; k++) {
            xout[3 * i + k] += g_dx[3 * i + k];
            g_dx[3 * i + k] = 0.f;
        }
        __syncwarp();
    }
}

// ---------------- launch ----------------
extern "C" void kernel_launch(void *const *d_in, const int *in_sizes, int n_in,
                              void *d_out, int out_size) {
    const float *x   = (const float *)d_in[0];
    const int   *z   = (const int *)d_in[1];
    const float *t   = (const float *)d_in[2];
    const int   *ei  = (const int *)d_in[3];
    const float *emb = (const float *)d_in[4];
    const float *tw1 = (const float *)d_in[5];
    const float *tb1 = (const float *)d_in[6];
    const float *tw2 = (const float *)d_in[7];
    const float *tb2 = (const float *)d_in[8];
    const float *ew1 = (const float *)d_in[9];
    const float *eb1 = (const float *)d_in[10];
    const float *ew2 = (const float *)d_in[11];
    const float *eb2 = (const float *)d_in[12];
    const float *cw1 = (const float *)d_in[13];
    const float *cb1 = (const float *)d_in[14];
    const float *cw2 = (const float *)d_in[15];
    const float *cb2 = (const float *)d_in[16];
    const float *nw1 = (const float *)d_in[17];
    const float *nb1 = (const float *)d_in[18];
    const float *nw2 = (const float *)d_in[19];
    const float *nb2 = (const float *)d_in[20];
    float *out = (float *)d_out;

    cudaFuncSetAttribute(edge_kernel, cudaFuncAttributeMaxDynamicSharedMemorySize,
                         EDGE_SMEM_BYTES);
    cudaFuncSetAttribute(node_kernel, cudaFuncAttributeMaxDynamicSharedMemorySize,
                         NODE_SMEM_BYTES);
    cudaFuncSetAttribute(pre0_kernel, cudaFuncAttributeMaxDynamicSharedMemorySize,
                         PRE_SMEM_BYTES);

    tmean_kernel<<<1, 64>>>(t, tw1, tb1, tw2, tb2);
    init_kernel<<<2048, 256>>>(x, z, emb, out);
    pre0_kernel<<<296, 256, PRE_SMEM_BYTES>>>(ew1, eb1);
    for (int l = 0; l < NLAYERS; l++) {
        edge_kernel<<<444, 256, EDGE_SMEM_BYTES>>>(
            out, ei, ew1 + l * 8256, ew2 + l * 4096, eb2 + l * 64,
            cw1 + l * 4096, cb1 + l * 64, cw2 + l * 64, cb2 + l);
        int do_pre = (l + 1 < NLAYERS);
        node_kernel<<<296, 256, NODE_SMEM_BYTES>>>(
            out, nw1 + l * 8192, nb1 + l * 64, nw2 + l * 4096, nb2 + l * 64,
            do_pre ? (ew1 + (l + 1) * 8256) : ew1,
            do_pre ? (eb1 + (l + 1) * 64) : eb1, do_pre);
    }
    (void)in_sizes; (void)n_in; (void)out_size;
}

// round 11
// speedup vs baseline: 1.2053x; 1.2053x over previous
#include <cuda_runtime.h>
#include <cuda_fp16.h>
#include <cstdint>

#define NN 100000
#define NE 1600000
#define HH 64
#define NLAYERS 3

// ---------------- device scratch ----------------
__device__ float4 g_h4[NN * 16];     // h: (N, 64) fp32
__device__ float4 g_agg4[NN * 16];   // agg: (N, 64) fp32
__device__ __half2 g_ah[NN * 32];    // a[n] = h[n] @ W1[0:64] + e_b1 (fp16)
__device__ __half2 g_bh[NN * 32];    // b[n] = h[n] @ W1[64:128]      (fp16)
__device__ float4 g_x4[NN];          // padded coords (x,y,z,0)
__device__ float  g_dx[NN * 3];
__device__ float4 g_tmean4[16];

// ---------------- helpers ----------------
__device__ __forceinline__ float siluf(float v) {
    float th;
    float hv = 0.5f * v;
    asm("tanh.approx.f32 %0, %1;" : "=f"(th) : "f"(hv));
    return fmaf(hv, th, hv);
}
__device__ __forceinline__ float silux(float v) {
    return __fdividef(v, 1.0f + __expf(-v));
}
__device__ __forceinline__ void red2(float *p, float a, float b) {
    asm volatile("red.global.add.v2.f32 [%0], {%1,%2};" ::"l"(p), "f"(a), "f"(b)
                 : "memory");
}
__device__ __forceinline__ void red1(float *p, float a) {
    asm volatile("red.global.add.f32 [%0], %1;" ::"l"(p), "f"(a) : "memory");
}
__device__ __forceinline__ uint32_t packh(float a, float b) {
    __half2 h = __floats2half2_rn(a, b);
    return *reinterpret_cast<uint32_t *>(&h);
}
// pair-slot index for fp16x2 word w (= k/2) within a row
__device__ __forceinline__ int pslot(int w) {
    return 8 * (w >> 3) + 2 * (w & 3) + ((w >> 2) & 1);
}
__device__ __forceinline__ void mma_f16(float (&d)[4], uint32_t a0, uint32_t a1,
                                        uint32_t a2, uint32_t a3, uint32_t b0,
                                        uint32_t b1) {
    asm volatile(
        "mma.sync.aligned.m16n8k16.row.col.f32.f16.f16.f32 "
        "{%0,%1,%2,%3}, {%4,%5,%6,%7}, {%8,%9}, {%0,%1,%2,%3};\n"
        : "+f"(d[0]), "+f"(d[1]), "+f"(d[2]), "+f"(d[3])
        : "r"(a0), "r"(a1), "r"(a2), "r"(a3), "r"(b0), "r"(b1));
}

// 32 x (16*KS16) A (smem) @ B (64 cols), fp16x2 pair-slot layout
template <int SA, int SB, int KS16>
__device__ __forceinline__ void gemmH(float (&acc)[2][8][4],
                                      const uint32_t *__restrict__ A,
                                      const uint32_t *__restrict__ B, int g,
                                      int q) {
#pragma unroll
    for (int ks = 0; ks < KS16; ks++) {
        uint2 bf[8];
#pragma unroll
        for (int n = 0; n < 8; n++)
            bf[n] = *(const uint2 *)(B + (8 * n + g) * SB + 8 * ks + 2 * q);
#pragma unroll
        for (int m = 0; m < 2; m++) {
            const uint32_t *ap = A + (16 * m + g) * SA + 8 * ks + 2 * q;
            uint2 lo = *(const uint2 *)ap;
            uint2 hi = *(const uint2 *)(ap + 8 * SA);
#pragma unroll
            for (int n = 0; n < 8; n++)
                mma_f16(acc[m][n], lo.x, hi.x, lo.y, hi.y, bf[n].x, bf[n].y);
        }
    }
}
// A from registers (C-fragment reuse): Ar[m][n][0]=rows-lo pack, [1]=rows-hi
template <int SB>
__device__ __forceinline__ void gemmR(float (&acc)[2][8][4],
                                      const uint32_t (&Ar)[2][8][2],
                                      const uint32_t *__restrict__ B, int g,
                                      int q) {
#pragma unroll
    for (int ks = 0; ks < 4; ks++) {
        uint2 bf[8];
#pragma unroll
        for (int n = 0; n < 8; n++)
            bf[n] = *(const uint2 *)(B + (8 * n + g) * SB + 8 * ks + 2 * q);
#pragma unroll
        for (int m = 0; m < 2; m++) {
#pragma unroll
            for (int n = 0; n < 8; n++)
                mma_f16(acc[m][n], Ar[m][2 * ks][0], Ar[m][2 * ks][1],
                        Ar[m][2 * ks + 1][0], Ar[m][2 * ks + 1][1], bf[n].x,
                        bf[n].y);
        }
    }
}
__device__ __forceinline__ void zacc(float (&acc)[2][8][4]) {
#pragma unroll
    for (int m = 0; m < 2; m++)
#pragma unroll
        for (int n = 0; n < 8; n++)
#pragma unroll
            for (int v = 0; v < 4; v++) acc[m][n][v] = 0.f;
}
__device__ __forceinline__ void cp_s(float *dst, const float *__restrict__ src,
                                     int nfloats, int tid, int nthr) {
    const float4 *s4 = (const float4 *)src;
    float4 *d4 = (float4 *)dst;
    for (int k = tid; k < (nfloats >> 2); k += nthr) d4[k] = s4[k];
}
// stage K x 64 row-major fp32 weights into fp16x2 pair-slot [64][stride]
__device__ __forceinline__ void stage_w16(uint32_t *dst, const float *__restrict__ W,
                                          int kwords, int stride, int tid,
                                          int nthr) {
    for (int idx = tid; idx < 64 * kwords; idx += nthr) {
        int n = idx / kwords, w = idx % kwords;
        dst[n * stride + pslot(w)] =
            packh(W[(2 * w) * 64 + n], W[(2 * w + 1) * 64 + n]);
    }
}

// ---------------- time-embedding mean ----------------
__global__ void tmean_kernel(const float *__restrict__ t,
                             const float *__restrict__ w1,
                             const float *__restrict__ b1,
                             const float *__restrict__ w2,
                             const float *__restrict__ b2) {
    __shared__ float sS[16 * 64];
    int j = threadIdx.x;
    float w1j = w1[j], b1j = b1[j];
    for (int b = 0; b < 16; b++) sS[b * 64 + j] = silux(t[b] * w1j + b1j);
    __syncthreads();
    float accm = 0.f;
    for (int b = 0; b < 16; b++) {
        float s = b2[j];
        for (int k = 0; k < 64; k++) s += sS[b * 64 + k] * w2[k * 64 + j];
        accm += s;
    }
    ((float *)g_tmean4)[j] = accm * (1.0f / 16.0f);
}

// ---------------- init ----------------
__global__ void init_kernel(const float *__restrict__ x, const int *__restrict__ z,
                            const float *__restrict__ emb, float *__restrict__ out) {
    int tid = blockIdx.x * blockDim.x + threadIdx.x;
    int stride = gridDim.x * blockDim.x;
    const float4 *emb4 = (const float4 *)emb;
    for (int idx = tid; idx < NN * 16; idx += stride) {
        int i = idx >> 4, qq = idx & 15;
        float4 e = emb4[z[i] * 16 + qq];
        float4 tm = g_tmean4[qq];
        float4 r;
        r.x = e.x + tm.x; r.y = e.y + tm.y; r.z = e.z + tm.z; r.w = e.w + tm.w;
        g_h4[idx] = r;
        g_agg4[idx] = make_float4(0.f, 0.f, 0.f, 0.f);
    }
    for (int idx = tid; idx < NN * 3; idx += stride) {
        out[idx] = x[idx];
        g_dx[idx] = 0.f;
    }
    for (int i = tid; i < NN; i += stride) {
        g_x4[i] = make_float4(x[3 * i], x[3 * i + 1], x[3 * i + 2], 0.f);
    }
}

// ---------------- pre0: a,b for layer 0 (fp16 tensor core) ----------------
#define PR_AT 0
#define PR_BT 2560
#define PR_EB1 5120
#define PR_WARP 5184
#define PR_WARP_WORDS 1280
#define PRE_SMEM_BYTES ((PR_WARP + 8 * PR_WARP_WORDS) * 4)

__global__ void __launch_bounds__(256, 2)
pre0_kernel(const float *__restrict__ W1, const float *__restrict__ B1) {
    extern __shared__ float sm[];
    uint32_t *smu = (uint32_t *)sm;
    int tid = threadIdx.x;
    stage_w16(smu + PR_AT, W1, 32, 40, tid, 256);
    stage_w16(smu + PR_BT, W1 + 64 * 64, 32, 40, tid, 256);
    cp_s(sm + PR_EB1, B1, 64, tid, 256);
    __syncthreads();

    const int lane = tid & 31, wid = tid >> 5;
    const int g = lane >> 2, q = lane & 3;
    uint32_t *buf = smu + PR_WARP + wid * PR_WARP_WORDS;
    const float *gh = (const float *)g_h4;
    const int sl = pslot(lane);

    int gwarp = blockIdx.x * 8 + wid;
    int nwarps = gridDim.x * 8;
    for (int i0 = gwarp * 32; i0 < NN; i0 += nwarps * 32) {
#pragma unroll
        for (int t = 0; t < 32; t++) {
            float2 hv = *(const float2 *)(gh + (size_t)(i0 + t) * HH + 2 * lane);
            buf[t * 40 + sl] = packh(hv.x, hv.y);
        }
        __syncwarp();
        float acc[2][8][4];
        zacc(acc);
        gemmH<40, 40, 4>(acc, buf, smu + PR_AT, g, q);
#pragma unroll
        for (int m = 0; m < 2; m++) {
            int r0 = 16 * m + g, r1 = r0 + 8;
#pragma unroll
            for (int n = 0; n < 8; n++) {
                int w = 4 * n + q;
                float2 bb = *(const float2 *)(sm + PR_EB1 + 2 * w);
                g_ah[(size_t)(i0 + r0) * 32 + w] =
                    __floats2half2_rn(acc[m][n][0] + bb.x, acc[m][n][1] + bb.y);
                g_ah[(size_t)(i0 + r1) * 32 + w] =
                    __floats2half2_rn(acc[m][n][2] + bb.x, acc[m][n][3] + bb.y);
            }
        }
        zacc(acc);
        gemmH<40, 40, 4>(acc, buf, smu + PR_BT, g, q);
#pragma unroll
        for (int m = 0; m < 2; m++) {
            int r0 = 16 * m + g, r1 = r0 + 8;
#pragma unroll
            for (int n = 0; n < 8; n++) {
                int w = 4 * n + q;
                g_bh[(size_t)(i0 + r0) * 32 + w] =
                    __floats2half2_rn(acc[m][n][0], acc[m][n][1]);
                g_bh[(size_t)(i0 + r1) * 32 + w] =
                    __floats2half2_rn(acc[m][n][2], acc[m][n][3]);
            }
        }
        __syncwarp();
    }
}

// ---------------- edge kernel (fp16 TC, per-warp batches, reg A-reuse) -----
#define E_W2T 0
#define E_C1T 2560
#define E_B2 5120
#define E_CB1 5184
#define E_C2 5248
#define E_W129 5312
#define E_CB2 5376
#define E_WARP 5384
#define E_WARP_WORDS 1312   /* m1s 1280 + cwbuf 32 */
#define EDGE_SMEM_BYTES ((E_WARP + 8 * E_WARP_WORDS) * 4)

__global__ void __launch_bounds__(256, 2)
edge_kernel(const int *__restrict__ ei, const float *__restrict__ W1,
            const float *__restrict__ W2, const float *__restrict__ B2,
            const float *__restrict__ C1, const float *__restrict__ Cb1,
            const float *__restrict__ C2, const float *__restrict__ Cb2) {
    extern __shared__ float sm[];
    uint32_t *smu = (uint32_t *)sm;
    int tid = threadIdx.x;

    stage_w16(smu + E_W2T, W2, 32, 40, tid, 256);
    stage_w16(smu + E_C1T, C1, 32, 40, tid, 256);
    cp_s(sm + E_B2, B2, 64, tid, 256);
    cp_s(sm + E_CB1, Cb1, 64, tid, 256);
    cp_s(sm + E_C2, C2, 64, tid, 256);
    cp_s(sm + E_W129, W1 + 8192, 64, tid, 256);
    if (tid == 0) sm[E_CB2] = Cb2[0];
    __syncthreads();

    const int lane = tid & 31;
    const int wid = tid >> 5;
    const int g = lane >> 2;
    const int q = lane & 3;
    uint32_t *m1s = smu + E_WARP + wid * E_WARP_WORDS;
    float *cwbuf = sm + E_WARP + wid * E_WARP_WORDS + 1280;
    const int sl = pslot(lane);

    float *gagg = (float *)g_agg4;

    const float w129x = sm[E_W129 + 2 * lane];
    const float w129y = sm[E_W129 + 2 * lane + 1];
    const float cb2v = sm[E_CB2];

    int gwarp = blockIdx.x * 8 + wid;
    int nwarps = gridDim.x * 8;

    for (int eb = gwarp * 32; eb < NE; eb += nwarps * 32) {
        int e = eb + lane;
        int s = ei[e];
        int d = ei[NE + e];
        float4 xd = g_x4[d];
        float4 xs = g_x4[s];
        float ax = xd.x - xs.x;
        float ay = xd.y - xs.y;
        float az = xd.z - xs.z;
        float d2 = ax * ax + ay * ay + az * az;

        // m1 = silu(a[d] + b[s] + d2*w129) -> staged fp16 pair-slot
#pragma unroll
        for (int t = 0; t < 32; t++) {
            int dt = __shfl_sync(0xffffffffu, d, t);
            int st = __shfl_sync(0xffffffffu, s, t);
            float d2t = __shfl_sync(0xffffffffu, d2, t);
            float2 av = __half22float2(g_ah[(size_t)dt * 32 + lane]);
            float2 bv = __half22float2(g_bh[(size_t)st * 32 + lane]);
            float m0 = siluf(fmaf(d2t, w129x, av.x + bv.x));
            float m1v = siluf(fmaf(d2t, w129y, av.y + bv.y));
            m1s[t * 40 + sl] = packh(m0, m1v);
        }
        __syncwarp();

        // GEMM2: m = silu(m1 @ W2 + b2)
        float acc[2][8][4];
        zacc(acc);
        gemmH<40, 40, 4>(acc, m1s, smu + E_W2T, g, q);

        // epilogue: silu, red2 agg scatter, pack m into A-fragments (regs)
        uint32_t mreg[2][8][2];
#pragma unroll
        for (int m = 0; m < 2; m++) {
            int r0 = 16 * m + g;
            int r1 = r0 + 8;
            int d0 = __shfl_sync(0xffffffffu, d, r0);
            int d1 = __shfl_sync(0xffffffffu, d, r1);
            float *agg0 = gagg + (size_t)d0 * HH;
            float *agg1 = gagg + (size_t)d1 * HH;
#pragma unroll
            for (int n = 0; n < 8; n++) {
                int c0 = 8 * n + 2 * q;
                float2 bb = *(const float2 *)(sm + E_B2 + c0);
                float v00 = siluf(acc[m][n][0] + bb.x);
                float v01 = siluf(acc[m][n][1] + bb.y);
                float v10 = siluf(acc[m][n][2] + bb.x);
                float v11 = siluf(acc[m][n][3] + bb.y);
                red2(agg0 + c0, v00, v01);
                red2(agg1 + c0, v10, v11);
                mreg[m][n][0] = packh(v00, v01);
                mreg[m][n][1] = packh(v10, v11);
            }
        }

        // coord MLP: cw = silu(m @ C1 + cb1) @ C2 + cb2 (A from registers)
        zacc(acc);
        gemmR<40>(acc, mreg, smu + E_C1T, g, q);

        float cwp[2][2] = {{0.f, 0.f}, {0.f, 0.f}};
#pragma unroll
        for (int m = 0; m < 2; m++)
#pragma unroll
            for (int n = 0; n < 8; n++) {
                int c0 = 8 * n + 2 * q;
                float2 cb1v = *(const float2 *)(sm + E_CB1 + c0);
                float2 c2v = *(const float2 *)(sm + E_C2 + c0);
                cwp[m][0] += siluf(acc[m][n][0] + cb1v.x) * c2v.x +
                             siluf(acc[m][n][1] + cb1v.y) * c2v.y;
                cwp[m][1] += siluf(acc[m][n][2] + cb1v.x) * c2v.x +
                             siluf(acc[m][n][3] + cb1v.y) * c2v.y;
            }
#pragma unroll
        for (int ofs = 1; ofs <= 2; ofs <<= 1) {
#pragma unroll
            for (int m = 0; m < 2; m++) {
                cwp[m][0] += __shfl_xor_sync(0xffffffffu, cwp[m][0], ofs);
                cwp[m][1] += __shfl_xor_sync(0xffffffffu, cwp[m][1], ofs);
            }
        }
        if (q == 0) {
#pragma unroll
            for (int m = 0; m < 2; m++) {
                cwbuf[16 * m + g] = cwp[m][0] + cb2v;
                cwbuf[16 * m + g + 8] = cwp[m][1] + cb2v;
            }
        }
        __syncwarp();

        float cw = cwbuf[lane];
        red1(&g_dx[3 * d + 0], ax * cw);
        red1(&g_dx[3 * d + 1], ay * cw);
        red1(&g_dx[3 * d + 2], az * cw);
        __syncwarp();
    }
}

// ---------------- node kernel (fp16 TC, split-K, reg A-reuse, 2 CTA/SM) ----
#define ND_W1A 0
#define ND_W1B 2560
#define ND_W2T 5120
#define ND_AT 7680
#define ND_BT 10240
#define ND_NB1 12800
#define ND_NB2 12864
#define ND_EB1 12928
#define ND_WARP 12992
#define ND_WARP_WORDS 1280
#define NODE_SMEM_BYTES ((ND_WARP + 8 * ND_WARP_WORDS) * 4)

__global__ void __launch_bounds__(256, 2)
node_kernel(float *__restrict__ xout, const float *__restrict__ NW1,
            const float *__restrict__ NB1, const float *__restrict__ NW2,
            const float *__restrict__ NB2, const float *__restrict__ EW1n,
            const float *__restrict__ EB1n, int do_pre) {
    extern __shared__ float sm[];
    uint32_t *smu = (uint32_t *)sm;
    int tid = threadIdx.x;

    stage_w16(smu + ND_W1A, NW1, 32, 40, tid, 256);           // nf rows 0..63 (h)
    stage_w16(smu + ND_W1B, NW1 + 64 * 64, 32, 40, tid, 256); // rows 64..127 (agg)
    stage_w16(smu + ND_W2T, NW2, 32, 40, tid, 256);
    if (do_pre) {
        stage_w16(smu + ND_AT, EW1n, 32, 40, tid, 256);
        stage_w16(smu + ND_BT, EW1n + 64 * 64, 32, 40, tid, 256);
    }
    cp_s(sm + ND_NB1, NB1, 64, tid, 256);
    cp_s(sm + ND_NB2, NB2, 64, tid, 256);
    if (do_pre) cp_s(sm + ND_EB1, EB1n, 64, tid, 256);
    __syncthreads();

    const int lane = tid & 31, wid = tid >> 5;
    const int g = lane >> 2, q = lane & 3;
    uint32_t *buf = smu + ND_WARP + wid * ND_WARP_WORDS;
    const int sl = pslot(lane);

    float *gh = (float *)g_h4;
    float *gagg = (float *)g_agg4;

    int gwarp = blockIdx.x * 8 + wid;
    int nwarps = gridDim.x * 8;

    for (int i0 = gwarp * 32; i0 < NN; i0 += nwarps * 32) {
        // stage h fp16 (stride 40)
#pragma unroll
        for (int t = 0; t < 32; t++) {
            float2 hv = *(const float2 *)(gh + (size_t)(i0 + t) * HH + 2 * lane);
            buf[t * 40 + sl] = packh(hv.x, hv.y);
        }
        __syncwarp();

        float acc[2][8][4];
        zacc(acc);
        gemmH<40, 40, 4>(acc, buf, smu + ND_W1A, g, q);
        __syncwarp();

        // stage agg fp16 (overwrite h staging); zero agg
#pragma unroll
        for (int t = 0; t < 32; t++) {
            size_t ro = (size_t)(i0 + t) * HH;
            float2 av = *(const float2 *)(gagg + ro + 2 * lane);
            *(float2 *)(gagg + ro + 2 * lane) = make_float2(0.f, 0.f);
            buf[t * 40 + sl] = packh(av.x, av.y);
        }
        __syncwarp();
        gemmH<40, 40, 4>(acc, buf, smu + ND_W1B, g, q);  // accumulate
        __syncwarp();

        // m1 = silu(acc + nb1) -> A-fragments in registers
        uint32_t mreg[2][8][2];
#pragma unroll
        for (int m = 0; m < 2; m++) {
#pragma unroll
            for (int n = 0; n < 8; n++) {
                int c0 = 8 * n + 2 * q;
                float2 bb = *(const float2 *)(sm + ND_NB1 + c0);
                mreg[m][n][0] = packh(siluf(acc[m][n][0] + bb.x),
                                      siluf(acc[m][n][1] + bb.y));
                mreg[m][n][1] = packh(siluf(acc[m][n][2] + bb.x),
                                      siluf(acc[m][n][3] + bb.y));
            }
        }

        zacc(acc);
        gemmR<40>(acc, mreg, smu + ND_W2T, g, q);

        // hnew = h_old + acc + nb2 -> global; pack hnew for pre gemms
#pragma unroll
        for (int m = 0; m < 2; m++) {
            int r0 = 16 * m + g, r1 = r0 + 8;
            float *h0 = gh + (size_t)(i0 + r0) * HH;
            float *h1 = gh + (size_t)(i0 + r1) * HH;
#pragma unroll
            for (int n = 0; n < 8; n++) {
                int c0 = 8 * n + 2 * q;
                float2 bb = *(const float2 *)(sm + ND_NB2 + c0);
                float2 o0 = *(const float2 *)(h0 + c0);
                float2 o1 = *(const float2 *)(h1 + c0);
                o0.x += acc[m][n][0] + bb.x;
                o0.y += acc[m][n][1] + bb.y;
                o1.x += acc[m][n][2] + bb.x;
                o1.y += acc[m][n][3] + bb.y;
                *(float2 *)(h0 + c0) = o0;
                *(float2 *)(h1 + c0) = o1;
                if (do_pre) {
                    mreg[m][n][0] = packh(o0.x, o0.y);
                    mreg[m][n][1] = packh(o1.x, o1.y);
                }
            }
        }

        if (do_pre) {
            zacc(acc);
            gemmR<40>(acc, mreg, smu + ND_AT, g, q);
#pragma unroll
            for (int m = 0; m < 2; m++) {
                int r0 = 16 * m + g, r1 = r0 + 8;
#pragma unroll
                for (int n = 0; n < 8; n++) {
                    int w = 4 * n + q;
                    float2 bb = *(const float2 *)(sm + ND_EB1 + 2 * w);
                    g_ah[(size_t)(i0 + r0) * 32 + w] = __floats2half2_rn(
                        acc[m][n][0] + bb.x, acc[m][n][1] + bb.y);
                    g_ah[(size_t)(i0 + r1) * 32 + w] = __floats2half2_rn(
                        acc[m][n][2] + bb.x, acc[m][n][3] + bb.y);
                }
            }
            zacc(acc);
            gemmR<40>(acc, mreg, smu + ND_BT, g, q);
#pragma unroll
            for (int m = 0; m < 2; m++) {
                int r0 = 16 * m + g, r1 = r0 + 8;
#pragma unroll
                for (int n = 0; n < 8; n++) {
                    int w = 4 * n + q;
                    g_bh[(size_t)(i0 + r0) * 32 + w] =
                        __floats2half2_rn(acc[m][n][0], acc[m][n][1]);
                    g_bh[(size_t)(i0 + r1) * 32 + w] =
                        __floats2half2_rn(acc[m][n][2], acc[m][n][3]);
                }
            }
        }

        // x += dx; update padded coords; reset dx (lane = node)
        int i = i0 + lane;
        float4 xv = g_x4[i];
        xv.x += g_dx[3 * i + 0];
        xv.y += g_dx[3 * i + 1];
        xv.z += g_dx[3 * i + 2];
        g_x4[i] = xv;
        xout[3 * i + 0] = xv.x;
        xout[3 * i + 1] = xv.y;
        xout[3 * i + 2] = xv.z;
        g_dx[3 * i + 0] = 0.f;
        g_dx[3 * i + 1] = 0.f;
        g_dx[3 * i + 2] = 0.f;
        __syncwarp();
    }
}

// ---------------- launch ----------------
extern "C" void kernel_launch(void *const *d_in, const int *in_sizes, int n_in,
                              void *d_out, int out_size) {
    const float *x   = (const float *)d_in[0];
    const int   *z   = (const int *)d_in[1];
    const float *t   = (const float *)d_in[2];
    const int   *ei  = (const int *)d_in[3];
    const float *emb = (const float *)d_in[4];
    const float *tw1 = (const float *)d_in[5];
    const float *tb1 = (const float *)d_in[6];
    const float *tw2 = (const float *)d_in[7];
    const float *tb2 = (const float *)d_in[8];
    const float *ew1 = (const float *)d_in[9];
    const float *eb1 = (const float *)d_in[10];
    const float *ew2 = (const float *)d_in[11];
    const float *eb2 = (const float *)d_in[12];
    const float *cw1 = (const float *)d_in[13];
    const float *cb1 = (const float *)d_in[14];
    const float *cw2 = (const float *)d_in[15];
    const float *cb2 = (const float *)d_in[16];
    const float *nw1 = (const float *)d_in[17];
    const float *nb1 = (const float *)d_in[18];
    const float *nw2 = (const float *)d_in[19];
    const float *nb2 = (const float *)d_in[20];
    float *out = (float *)d_out;

    cudaFuncSetAttribute(edge_kernel, cudaFuncAttributeMaxDynamicSharedMemorySize,
                         EDGE_SMEM_BYTES);
    cudaFuncSetAttribute(node_kernel, cudaFuncAttributeMaxDynamicSharedMemorySize,
                         NODE_SMEM_BYTES);
    cudaFuncSetAttribute(pre0_kernel, cudaFuncAttributeMaxDynamicSharedMemorySize,
                         PRE_SMEM_BYTES);

    tmean_kernel<<<1, 64>>>(t, tw1, tb1, tw2, tb2);
    init_kernel<<<2048, 256>>>(x, z, emb, out);
    pre0_kernel<<<296, 256, PRE_SMEM_BYTES>>>(ew1, eb1);
    for (int l = 0; l < NLAYERS; l++) {
        edge_kernel<<<296, 256, EDGE_SMEM_BYTES>>>(
            ei, ew1 + l * 8256, ew2 + l * 4096, eb2 + l * 64,
            cw1 + l * 4096, cb1 + l * 64, cw2 + l * 64, cb2 + l);
        int do_pre = (l + 1 < NLAYERS);
        node_kernel<<<296, 256, NODE_SMEM_BYTES>>>(
            out, nw1 + l * 8192, nb1 + l * 64, nw2 + l * 4096, nb2 + l * 64,
            do_pre ? (ew1 + (l + 1) * 8256) : ew1,
            do_pre ? (eb1 + (l + 1) * 64) : eb1, do_pre);
    }
    (void)in_sizes; (void)n_in; (void)out_size;
}